// round 1
// baseline (speedup 1.0000x reference)
#include <cuda_runtime.h>

#define BATCH 4096
#define DIM   4096
#define MARGIN 0.5f

// scratch for per-row hinge losses (allocation-free rule: __device__ global)
__device__ float g_partial[BATCH];

// ---------------------------------------------------------------------------
// Kernel 1: one CTA per row. Computes s1 = ||f_i - f_idx1||^2,
// s2 = ||f_i - f_idx2||^2, then the label/margin logic and hinge.
// 256 threads, float4 loads: each thread handles 4 float4 per operand row.
// ---------------------------------------------------------------------------
__global__ __launch_bounds__(256, 8)
void triplet_rows_kernel(const float* __restrict__ f,
                         const float* __restrict__ label,
                         const int*   __restrict__ idx1,
                         const int*   __restrict__ idx2)
{
    const int i = blockIdx.x;
    const int t = threadIdx.x;

    const int j1 = __ldg(&idx1[i]);
    const int j2 = __ldg(&idx2[i]);

    const float4* __restrict__ a  = (const float4*)(f + (size_t)i  * DIM);
    const float4* __restrict__ b1 = (const float4*)(f + (size_t)j1 * DIM);
    const float4* __restrict__ b2 = (const float4*)(f + (size_t)j2 * DIM);

    float s1 = 0.0f, s2 = 0.0f;

    // DIM/4 = 1024 float4 per row; 256 threads -> 4 iters
    #pragma unroll
    for (int k = 0; k < 4; k++) {
        const int idx = t + k * 256;
        const float4 av = __ldg(&a[idx]);
        const float4 v1 = __ldg(&b1[idx]);
        const float4 v2 = __ldg(&b2[idx]);
        float d;
        d = av.x - v1.x; s1 = fmaf(d, d, s1);
        d = av.y - v1.y; s1 = fmaf(d, d, s1);
        d = av.z - v1.z; s1 = fmaf(d, d, s1);
        d = av.w - v1.w; s1 = fmaf(d, d, s1);
        d = av.x - v2.x; s2 = fmaf(d, d, s2);
        d = av.y - v2.y; s2 = fmaf(d, d, s2);
        d = av.z - v2.z; s2 = fmaf(d, d, s2);
        d = av.w - v2.w; s2 = fmaf(d, d, s2);
    }

    // warp-level reduce
    #pragma unroll
    for (int off = 16; off > 0; off >>= 1) {
        s1 += __shfl_down_sync(0xFFFFFFFFu, s1, off);
        s2 += __shfl_down_sync(0xFFFFFFFFu, s2, off);
    }

    __shared__ float sh1[8], sh2[8];
    const int wid = t >> 5;
    const int lid = t & 31;
    if (lid == 0) { sh1[wid] = s1; sh2[wid] = s2; }
    __syncthreads();

    if (t == 0) {
        float t1 = 0.0f, t2 = 0.0f;
        #pragma unroll
        for (int w = 0; w < 8; w++) { t1 += sh1[w]; t2 += sh2[w]; }

        const float l  = __ldg(&label[i]);
        const float l1 = __ldg(&label[j1]);
        const float l2 = __ldg(&label[j2]);
        const float d1 = fabsf(l - l1);
        const float d2 = fabsf(l - l2);
        const bool cond = (d1 >= d2);       // true -> idx2 is the near sample

        const float a2n    = cond ? t2 : t1;
        const float a2f    = cond ? t1 : t2;
        const float near_l = cond ? l2 : l1;
        const float far_l  = cond ? l1 : l2;

        const float dn = l - near_l;
        const float df = l - far_l;
        const float alpha = df * df - dn * dn;
        const float loss = a2n - a2f + alpha * MARGIN;
        g_partial[i] = fmaxf(loss, 0.0f);
    }
}

// ---------------------------------------------------------------------------
// Kernel 2: deterministic single-block tree reduction of 4096 partials.
// ---------------------------------------------------------------------------
__global__ __launch_bounds__(1024, 1)
void reduce_kernel(float* __restrict__ out)
{
    const int t = threadIdx.x;
    float s = 0.0f;
    #pragma unroll
    for (int k = 0; k < 4; k++)
        s += g_partial[t + k * 1024];

    __shared__ float sh[1024];
    sh[t] = s;
    __syncthreads();

    #pragma unroll
    for (int stride = 512; stride > 0; stride >>= 1) {
        if (t < stride) sh[t] += sh[t + stride];
        __syncthreads();
    }
    if (t == 0) out[0] = sh[0];
}

extern "C" void kernel_launch(void* const* d_in, const int* in_sizes, int n_in,
                              void* d_out, int out_size)
{
    const float* f     = (const float*)d_in[0];
    const float* label = (const float*)d_in[1];
    const int*   idx1  = (const int*)d_in[2];
    const int*   idx2  = (const int*)d_in[3];
    float* out = (float*)d_out;

    triplet_rows_kernel<<<BATCH, 256>>>(f, label, idx1, idx2);
    reduce_kernel<<<1, 1024>>>(out);
}